// round 2
// baseline (speedup 1.0000x reference)
#include <cuda_runtime.h>

// ============================================================================
// Triple table (l1, l2, l3), all parity-even couplings with l1,l2 in 0..3,
// l3 in |l1-l2| .. min(l1+l2, 4). Order fixed; offsets derived from it.
// ============================================================================
#define NTRI 27

struct Tri { int l1, l2, l3; };
constexpr Tri TRS[NTRI] = {
  {0,0,0},{0,1,1},{0,2,2},{0,3,3},
  {1,0,1},{1,1,0},{1,1,2},{1,2,1},{1,2,3},{1,3,2},{1,3,4},
  {2,0,2},{2,1,1},{2,1,3},{2,2,0},{2,2,2},{2,2,4},{2,3,1},{2,3,3},
  {3,0,3},{3,1,2},{3,1,4},{3,2,1},{3,2,3},{3,3,0},{3,3,2},{3,3,4}
};

__host__ __device__ constexpr int tsz(int t) {
  return (2*TRS[t].l1+1)*(2*TRS[t].l2+1)*(2*TRS[t].l3+1);
}
__host__ __device__ constexpr int woff(int t) {
  int s = 0; for (int u = 0; u < t; ++u) s += tsz(u); return s;
}
constexpr int WTOT = woff(NTRI);   // 2919 floats

// Runtime copy for the init kernel
__constant__ int c_tri[NTRI][3] = {
  {0,0,0},{0,1,1},{0,2,2},{0,3,3},
  {1,0,1},{1,1,0},{1,1,2},{1,2,1},{1,2,3},{1,3,2},{1,3,4},
  {2,0,2},{2,1,1},{2,1,3},{2,2,0},{2,2,2},{2,2,4},{2,3,1},{2,3,3},
  {3,0,3},{3,1,2},{3,1,4},{3,2,1},{3,2,3},{3,3,0},{3,3,2},{3,3,4}
};

// Scratch: dense real Wigner-3j tensors, unit Frobenius norm per triple.
__device__ float g_w3j[WTOT];

// ============================================================================
// Init kernel: compute real-basis Wigner 3j coefficients (fp32).
// One block per triple. Runs every launch (deterministic, ~µs).
// ============================================================================
struct Cf { float x, y; };
__device__ __forceinline__ Cf cmulf(Cf a, Cf b) {
  return Cf{ a.x*b.x - a.y*b.y, a.x*b.y + a.y*b.x };
}

// Nonzero entries of column c of the real->complex change-of-basis Q for
// angular momentum l (incl. the (-i)^l phase). Each column has <= 2 entries.
__device__ __forceinline__ int qcolf(int l, int c, int* mr, Cf* vr) {
  const float is2 = 0.70710678118654752440f;
  int mu = c - l;
  int cnt;
  if (mu == 0) {
    mr[0] = 0; vr[0] = Cf{1.f, 0.f}; cnt = 1;
  } else if (mu > 0) {
    mr[0] = -mu; vr[0] = Cf{is2, 0.f};
    mr[1] =  mu; vr[1] = Cf{(mu & 1) ? -is2 : is2, 0.f};
    cnt = 2;
  } else {
    int am = -mu;
    mr[0] = -am; vr[0] = Cf{0.f, -is2};
    mr[1] =  am; vr[1] = Cf{0.f, (am & 1) ? -is2 : is2};
    cnt = 2;
  }
  Cf ph;
  switch (l & 3) {
    case 0:  ph = Cf{ 1.f,  0.f}; break;
    case 1:  ph = Cf{ 0.f, -1.f}; break;
    case 2:  ph = Cf{-1.f,  0.f}; break;
    default: ph = Cf{ 0.f,  1.f}; break;
  }
  for (int t = 0; t < cnt; ++t) vr[t] = cmulf(vr[t], ph);
  return cnt;
}

// SU(2) Clebsch-Gordan coefficient (Racah formula), fp32 with factorial table.
__device__ __forceinline__ float cgc_f(int j1, int m1, int j2, int m2,
                                       int j3, int m3, const float* ft) {
  if (m1 + m2 != m3) return 0.f;
  int vmin = -j1 + j2 + m3; if (-j1 + m1 > vmin) vmin = -j1 + m1; if (vmin < 0) vmin = 0;
  int vmax = j2 + j3 + m1;
  if (j3 - j1 + j2 < vmax) vmax = j3 - j1 + j2;
  if (j3 + m3 < vmax)      vmax = j3 + m3;
  if (vmax < vmin) return 0.f;
  float C = sqrtf((2.f*j3 + 1.f) * ft[j3+j1-j2] * ft[j3-j1+j2] * ft[j1+j2-j3]
                  * ft[j3+m3] * ft[j3-m3]
                  / (ft[j1+j2+j3+1] * ft[j1-m1] * ft[j1+m1] * ft[j2-m2] * ft[j2+m2]));
  float S = 0.f;
  for (int v = vmin; v <= vmax; ++v) {
    float t = ft[j2+j3+m1-v] * ft[j1-m1+v]
            / (ft[v] * ft[j3-j1+j2-v] * ft[j3+m3-v] * ft[j1-j2-m3+v]);
    S += ((v + j2 + m2) & 1) ? -t : t;
  }
  return C * S;
}

__global__ void w3j_init_kernel() {
  int T = blockIdx.x;
  int l1 = c_tri[T][0], l2 = c_tri[T][1], l3 = c_tri[T][2];
  int n1 = 2*l1 + 1, n2 = 2*l2 + 1, n3 = 2*l3 + 1;
  int sz = n1 * n2 * n3;
  int base = 0;
  for (int u = 0; u < T; ++u)
    base += (2*c_tri[u][0] + 1) * (2*c_tri[u][1] + 1) * (2*c_tri[u][2] + 1);

  float ft[12];
  ft[0] = 1.f;
  for (int i = 1; i < 12; ++i) ft[i] = ft[i-1] * (float)i;

  float vals[2]; int eidx[2]; int cnt = 0;
  float sq = 0.f;
  for (int e = threadIdx.x; e < sz; e += blockDim.x) {
    int c1 = e / (n2 * n3);
    int r  = e - c1 * n2 * n3;
    int c2 = r / n3;
    int c3 = r - c2 * n3;
    int m1s[2], m2s[2], m3s[2];
    Cf v1[2], v2[2], v3[2];
    int q1 = qcolf(l1, c1, m1s, v1);
    int q2 = qcolf(l2, c2, m2s, v2);
    int q3 = qcolf(l3, c3, m3s, v3);
    Cf acc = Cf{0.f, 0.f};
    for (int x = 0; x < q1; ++x)
      for (int y = 0; y < q2; ++y)
        for (int z = 0; z < q3; ++z) {
          float cg = cgc_f(l1, m1s[x], l2, m2s[y], l3, m3s[z], ft);
          if (cg != 0.f) {
            Cf q = cmulf(cmulf(v1[x], v2[y]), v3[z]);
            acc.x += q.x * cg;
            acc.y += q.y * cg;
          }
        }
    vals[cnt] = acc.x; eidx[cnt] = e; ++cnt;
    sq += acc.x * acc.x;
  }

  __shared__ float red[256];
  red[threadIdx.x] = sq;
  __syncthreads();
  for (int s = 128; s > 0; s >>= 1) {
    if (threadIdx.x < (unsigned)s) red[threadIdx.x] += red[threadIdx.x + s];
    __syncthreads();
  }
  float nrm = sqrtf(red[0]);
  float inv = (nrm > 0.f) ? 1.f / nrm : 0.f;
  for (int t = 0; t < cnt; ++t) g_w3j[base + eidx[t]] = vals[t] * inv;
}

// ============================================================================
// Main kernel: fused tensor product, one thread per (node, channel) item.
// ============================================================================

// Exact real-basis nonzero pattern: sin/cos azimuthal selection rules.
__host__ __device__ constexpr bool nzpat(int l1, int i, int l2, int j, int l3, int k) {
  const int u1 = i - l1, u2 = j - l2, u3 = k - l3;
  const int a1 = u1 < 0 ? -u1 : u1;
  const int a2 = u2 < 0 ? -u2 : u2;
  const int a3 = u3 < 0 ? -u3 : u3;
  const int neg = (u1 < 0 ? 1 : 0) + (u2 < 0 ? 1 : 0) + (u3 < 0 ? 1 : 0);
  const int d = a1 > a2 ? a1 - a2 : a2 - a1;
  return !(neg & 1) && (a3 == a1 + a2 || a3 == d);
}

template <int T>
__device__ __forceinline__ void tri_contract(const float* __restrict__ ws,
                                             const float (&a)[16],
                                             const float (&b)[16],
                                             float (&acc)[25]) {
  constexpr int l1 = TRS[T].l1, l2 = TRS[T].l2, l3 = TRS[T].l3;
  // Permutation symmetry: for even parity, w3j(l2,l1,l3)[j,i,k] == w3j(l1,l2,l3)[i,j,k].
  // Process only l1 <= l2 and fold the swapped triple into a symmetrized product.
  if constexpr (l1 <= l2) {
    constexpr int n1 = 2*l1 + 1, n2 = 2*l2 + 1, n3 = 2*l3 + 1;
    constexpr int o1 = l1*l1, o2 = l2*l2, o3 = l3*l3;
    constexpr int wo = woff(T);
    #pragma unroll
    for (int i = 0; i < n1; ++i) {
      #pragma unroll
      for (int j = 0; j < n2; ++j) {
        if (l1 == l2 && j < i) continue;   // diagonal i<=j folding
        float p;
        if (l1 == l2) {
          p = (j == i) ? a[o1 + i] * b[o2 + i]
                       : a[o1 + i] * b[o2 + j] + a[o1 + j] * b[o2 + i];
        } else {
          p = a[o1 + i] * b[o2 + j] + a[o2 + j] * b[o1 + i];
        }
        #pragma unroll
        for (int k = 0; k < n3; ++k) {
          if (nzpat(l1, i, l2, j, l3, k)) {
            acc[o3 + k] = fmaf(p, ws[wo + (i*n2 + j)*n3 + k], acc[o3 + k]);
          }
        }
      }
    }
  }
}

template <int T>
__device__ __forceinline__ void contract_from(const float* __restrict__ ws,
                                              const float (&a)[16],
                                              const float (&b)[16],
                                              float (&acc)[25]) {
  if constexpr (T < NTRI) {
    tri_contract<T>(ws, a, b, acc);
    contract_from<T + 1>(ws, a, b, acc);
  }
}

__global__ __launch_bounds__(256)
void tp_kernel(const float* __restrict__ A, const float* __restrict__ B,
               float* __restrict__ O, int nitems) {
  __shared__ float  ws[WTOT];
  __shared__ float4 so4[256 * 25 / 4];   // 1600 float4 output staging
  float* so = reinterpret_cast<float*>(so4);

  for (int s = threadIdx.x; s < WTOT; s += 256) ws[s] = g_w3j[s];
  __syncthreads();

  for (int base = blockIdx.x * 256; base < nitems; base += gridDim.x * 256) {
    int item = base + (int)threadIdx.x;
    bool valid = item < nitems;
    float a[16], b[16], acc[25];

    if (valid) {
      const float4* pa = reinterpret_cast<const float4*>(A) + (size_t)item * 4;
      const float4* pb = reinterpret_cast<const float4*>(B) + (size_t)item * 4;
      float4 v;
      v = pa[0]; a[ 0]=v.x; a[ 1]=v.y; a[ 2]=v.z; a[ 3]=v.w;
      v = pa[1]; a[ 4]=v.x; a[ 5]=v.y; a[ 6]=v.z; a[ 7]=v.w;
      v = pa[2]; a[ 8]=v.x; a[ 9]=v.y; a[10]=v.z; a[11]=v.w;
      v = pa[3]; a[12]=v.x; a[13]=v.y; a[14]=v.z; a[15]=v.w;
      v = pb[0]; b[ 0]=v.x; b[ 1]=v.y; b[ 2]=v.z; b[ 3]=v.w;
      v = pb[1]; b[ 4]=v.x; b[ 5]=v.y; b[ 6]=v.z; b[ 7]=v.w;
      v = pb[2]; b[ 8]=v.x; b[ 9]=v.y; b[10]=v.z; b[11]=v.w;
      v = pb[3]; b[12]=v.x; b[13]=v.y; b[14]=v.z; b[15]=v.w;
      #pragma unroll
      for (int k = 0; k < 25; ++k) acc[k] = 0.f;
      contract_from<0>(ws, a, b, acc);
    }

    __syncthreads();   // previous chunk's staging reads are done
    if (valid) {
      #pragma unroll
      for (int k = 0; k < 25; ++k) so[threadIdx.x * 25 + k] = acc[k];
    }
    __syncthreads();

    int vcnt = nitems - base;
    if (vcnt > 256) vcnt = 256;
    if (vcnt == 256) {
      float4* ov = reinterpret_cast<float4*>(O + (size_t)base * 25);
      for (int r = threadIdx.x; r < 1600; r += 256) ov[r] = so4[r];
    } else {
      int cnt = vcnt * 25;
      float* op = O + (size_t)base * 25;
      for (int r = threadIdx.x; r < cnt; r += 256) op[r] = so[r];
    }
  }
}

// ============================================================================
// Launch
// ============================================================================
extern "C" void kernel_launch(void* const* d_in, const int* in_sizes, int n_in,
                              void* d_out, int out_size) {
  const float* A = (const float*)d_in[0];
  const float* B = (const float*)d_in[1];
  float* O = (float*)d_out;
  int nitems = in_sizes[0] / 16;
  if (nitems <= 0) return;

  w3j_init_kernel<<<NTRI, 256>>>();

  int chunks = (nitems + 255) / 256;
  int grid = chunks < 592 ? chunks : 592;
  tp_kernel<<<grid, 256>>>(A, B, O, nitems);
}

// round 4
// speedup vs baseline: 1.4316x; 1.4316x over previous
#include <cuda_runtime.h>

// ============================================================================
// Compile-time real Wigner-3j coefficients.
// All math in constexpr double; values baked into SASS as FFMA immediates.
// All helpers are __host__ __device__ so nvcc accepts compile-time evaluation
// from device contexts without --expt-relaxed-constexpr.
// ============================================================================
#define NTRI 27

struct Tri { int l1, l2, l3; };
constexpr Tri TRS[NTRI] = {
  {0,0,0},{0,1,1},{0,2,2},{0,3,3},
  {1,0,1},{1,1,0},{1,1,2},{1,2,1},{1,2,3},{1,3,2},{1,3,4},
  {2,0,2},{2,1,1},{2,1,3},{2,2,0},{2,2,2},{2,2,4},{2,3,1},{2,3,3},
  {3,0,3},{3,1,2},{3,1,4},{3,2,1},{3,2,3},{3,3,0},{3,3,2},{3,3,4}
};

__host__ __device__ constexpr double cfact(int n) {
  double r = 1.0;
  for (int i = 2; i <= n; ++i) r *= (double)i;
  return r;
}

__host__ __device__ constexpr double csqrt_(double x) {
  if (x <= 0.0) return 0.0;
  double g = x > 1.0 ? x : 1.0;
  for (int i = 0; i < 80; ++i) g = 0.5 * (g + x / g);
  return g;
}

struct CD { double re, im; };
__host__ __device__ constexpr CD cmul_(CD a, CD b) {
  return CD{ a.re*b.re - a.im*b.im, a.re*b.im + a.im*b.re };
}

struct QCol { int cnt; int m[2]; CD v[2]; };

// Nonzero entries of column c of the real->complex basis change Q_l (incl (-i)^l).
__host__ __device__ constexpr QCol qcol(int l, int c) {
  QCol q{};
  const double is2 = 0.70710678118654752440;
  int mu = c - l;
  if (mu == 0) {
    q.cnt = 1; q.m[0] = 0; q.v[0] = CD{1.0, 0.0};
  } else if (mu > 0) {
    q.cnt = 2;
    q.m[0] = -mu; q.v[0] = CD{is2, 0.0};
    q.m[1] =  mu; q.v[1] = CD{(mu & 1) ? -is2 : is2, 0.0};
  } else {
    int am = -mu;
    q.cnt = 2;
    q.m[0] = -am; q.v[0] = CD{0.0, -is2};
    q.m[1] =  am; q.v[1] = CD{0.0, (am & 1) ? -is2 : is2};
  }
  CD ph{1.0, 0.0};
  switch (l & 3) {
    case 0: ph = CD{ 1.0,  0.0}; break;
    case 1: ph = CD{ 0.0, -1.0}; break;
    case 2: ph = CD{-1.0,  0.0}; break;
    default: ph = CD{ 0.0,  1.0}; break;
  }
  for (int t = 0; t < q.cnt; ++t) q.v[t] = cmul_(q.v[t], ph);
  return q;
}

// SU(2) Clebsch-Gordan (Racah formula), constexpr double.
__host__ __device__ constexpr double cgc(int j1, int m1, int j2, int m2, int j3, int m3) {
  if (m1 + m2 != m3) return 0.0;
  int vmin = -j1 + j2 + m3;
  if (-j1 + m1 > vmin) vmin = -j1 + m1;
  if (vmin < 0) vmin = 0;
  int vmax = j2 + j3 + m1;
  if (j3 - j1 + j2 < vmax) vmax = j3 - j1 + j2;
  if (j3 + m3 < vmax)      vmax = j3 + m3;
  if (vmax < vmin) return 0.0;
  double C = csqrt_((2.0*j3 + 1.0) * cfact(j3+j1-j2) * cfact(j3-j1+j2) * cfact(j1+j2-j3)
                    * cfact(j3+m3) * cfact(j3-m3)
                    / (cfact(j1+j2+j3+1) * cfact(j1-m1) * cfact(j1+m1)
                       * cfact(j2-m2) * cfact(j2+m2)));
  double S = 0.0;
  for (int v = vmin; v <= vmax; ++v) {
    double t = cfact(j2+j3+m1-v) * cfact(j1-m1+v)
             / (cfact(v) * cfact(j3-j1+j2-v) * cfact(j3+m3-v) * cfact(j1-j2-m3+v));
    S += ((v + j2 + m2) & 1) ? -t : t;
  }
  return C * S;
}

// Raw (unnormalized) real-basis 3j entry: Re( Q1[:,i] Q2[:,j] Q3[:,k] . CG ).
__host__ __device__ constexpr double w3j_raw(int l1, int l2, int l3, int i, int j, int k) {
  QCol q1 = qcol(l1, i), q2 = qcol(l2, j), q3 = qcol(l3, k);
  CD acc{0.0, 0.0};
  for (int x = 0; x < q1.cnt; ++x)
    for (int y = 0; y < q2.cnt; ++y)
      for (int z = 0; z < q3.cnt; ++z) {
        double cg = cgc(l1, q1.m[x], l2, q2.m[y], l3, q3.m[z]);
        if (cg != 0.0) {
          CD t = cmul_(cmul_(q1.v[x], q2.v[y]), q3.v[z]);
          acc.re += t.re * cg;
          acc.im += t.im * cg;
        }
      }
  return acc.re;
}

__host__ __device__ constexpr double w3j_norm(int l1, int l2, int l3) {
  double s = 0.0;
  int n1 = 2*l1 + 1, n2 = 2*l2 + 1, n3 = 2*l3 + 1;
  for (int i = 0; i < n1; ++i)
    for (int j = 0; j < n2; ++j)
      for (int k = 0; k < n3; ++k) {
        double v = w3j_raw(l1, l2, l3, i, j, k);
        s += v * v;
      }
  return csqrt_(s);
}

// ============================================================================
// Contraction via template recursion (all indices compile-time constants).
// Permutation symmetry: for even parity w3j(l2,l1,l3)[j,i,k] == w3j(l1,l2,l3)[i,j,k],
// so only l1<=l2 triples are processed, with symmetrized products.
// ============================================================================

template <int T, int I, int J, int K>
__device__ __forceinline__ void kstep(float p, float (&acc)[25]) {
  constexpr int l1 = TRS[T].l1, l2 = TRS[T].l2, l3 = TRS[T].l3;
  constexpr int n3 = 2*l3 + 1, o3 = l3*l3;
  if constexpr (K < n3) {
    constexpr double wr = w3j_raw(l1, l2, l3, I, J, K);
    if constexpr (wr > 1e-12 || wr < -1e-12) {
      constexpr float w = (float)(wr / w3j_norm(l1, l2, l3));
      acc[o3 + K] = fmaf(p, w, acc[o3 + K]);
    }
    kstep<T, I, J, K + 1>(p, acc);
  }
}

template <int T, int I, int J>
__device__ __forceinline__ void jstep(const float (&a)[16], const float (&b)[16],
                                      float (&acc)[25]) {
  constexpr int l1 = TRS[T].l1, l2 = TRS[T].l2;
  constexpr int n2 = 2*l2 + 1, o1 = l1*l1, o2 = l2*l2;
  if constexpr (J < n2) {
    if constexpr (!(l1 == l2 && J < I)) {   // diagonal i<=j folding
      float p;
      if constexpr (l1 == l2) {
        if constexpr (J == I) p = a[o1 + I] * b[o2 + I];
        else                  p = a[o1 + I] * b[o2 + J] + a[o1 + J] * b[o2 + I];
      } else {
        p = a[o1 + I] * b[o2 + J] + a[o2 + J] * b[o1 + I];
      }
      kstep<T, I, J, 0>(p, acc);
    }
    jstep<T, I, J + 1>(a, b, acc);
  }
}

template <int T, int I>
__device__ __forceinline__ void istep(const float (&a)[16], const float (&b)[16],
                                      float (&acc)[25]) {
  constexpr int n1 = 2*TRS[T].l1 + 1;
  if constexpr (I < n1) {
    jstep<T, I, 0>(a, b, acc);
    istep<T, I + 1>(a, b, acc);
  }
}

template <int T>
__device__ __forceinline__ void contract_from(const float (&a)[16], const float (&b)[16],
                                              float (&acc)[25]) {
  if constexpr (T < NTRI) {
    if constexpr (TRS[T].l1 <= TRS[T].l2) {
      istep<T, 0>(a, b, acc);
    }
    contract_from<T + 1>(a, b, acc);
  }
}

// ============================================================================
// Main kernel: one thread per (node, channel) item; smem-staged coalesced output.
// ============================================================================
__global__ __launch_bounds__(256)
void tp_kernel(const float* __restrict__ A, const float* __restrict__ B,
               float* __restrict__ O, int nitems) {
  __shared__ float4 so4[256 * 25 / 4];   // 1600 float4 output staging
  float* so = reinterpret_cast<float*>(so4);

  for (int base = blockIdx.x * 256; base < nitems; base += gridDim.x * 256) {
    int item = base + (int)threadIdx.x;
    bool valid = item < nitems;
    float a[16], b[16], acc[25];

    if (valid) {
      const float4* pa = reinterpret_cast<const float4*>(A) + (size_t)item * 4;
      const float4* pb = reinterpret_cast<const float4*>(B) + (size_t)item * 4;
      float4 v;
      v = pa[0]; a[ 0]=v.x; a[ 1]=v.y; a[ 2]=v.z; a[ 3]=v.w;
      v = pa[1]; a[ 4]=v.x; a[ 5]=v.y; a[ 6]=v.z; a[ 7]=v.w;
      v = pa[2]; a[ 8]=v.x; a[ 9]=v.y; a[10]=v.z; a[11]=v.w;
      v = pa[3]; a[12]=v.x; a[13]=v.y; a[14]=v.z; a[15]=v.w;
      v = pb[0]; b[ 0]=v.x; b[ 1]=v.y; b[ 2]=v.z; b[ 3]=v.w;
      v = pb[1]; b[ 4]=v.x; b[ 5]=v.y; b[ 6]=v.z; b[ 7]=v.w;
      v = pb[2]; b[ 8]=v.x; b[ 9]=v.y; b[10]=v.z; b[11]=v.w;
      v = pb[3]; b[12]=v.x; b[13]=v.y; b[14]=v.z; b[15]=v.w;
      #pragma unroll
      for (int k = 0; k < 25; ++k) acc[k] = 0.f;
      contract_from<0>(a, b, acc);
    }

    __syncthreads();   // previous chunk's staging reads are done
    if (valid) {
      #pragma unroll
      for (int k = 0; k < 25; ++k) so[threadIdx.x * 25 + k] = acc[k];
    }
    __syncthreads();

    int vcnt = nitems - base;
    if (vcnt > 256) vcnt = 256;
    if (vcnt == 256) {
      float4* ov = reinterpret_cast<float4*>(O + (size_t)base * 25);
      #pragma unroll
      for (int r = 0; r < 1600 / 256; ++r)
        ov[r * 256 + threadIdx.x] = so4[r * 256 + threadIdx.x];
      if (threadIdx.x < 1600 - (1600 / 256) * 256)
        ov[(1600 / 256) * 256 + threadIdx.x] = so4[(1600 / 256) * 256 + threadIdx.x];
    } else {
      int cnt = vcnt * 25;
      float* op = O + (size_t)base * 25;
      for (int r = threadIdx.x; r < cnt; r += 256) op[r] = so[r];
    }
  }
}

// ============================================================================
// Launch
// ============================================================================
extern "C" void kernel_launch(void* const* d_in, const int* in_sizes, int n_in,
                              void* d_out, int out_size) {
  const float* A = (const float*)d_in[0];
  const float* B = (const float*)d_in[1];
  float* O = (float*)d_out;
  int nitems = in_sizes[0] / 16;
  if (nitems <= 0) return;

  int chunks = (nitems + 255) / 256;
  int grid = chunks < 592 ? chunks : 592;
  tp_kernel<<<grid, 256>>>(A, B, O, nitems);
}

// round 5
// speedup vs baseline: 1.6089x; 1.1238x over previous
#include <cuda_runtime.h>

// ============================================================================
// Compile-time real Wigner-3j coefficients.
// All math in constexpr double; values baked into SASS as FFMA immediates.
// ============================================================================
#define NTRI 27

struct Tri { int l1, l2, l3; };
constexpr Tri TRS[NTRI] = {
  {0,0,0},{0,1,1},{0,2,2},{0,3,3},
  {1,0,1},{1,1,0},{1,1,2},{1,2,1},{1,2,3},{1,3,2},{1,3,4},
  {2,0,2},{2,1,1},{2,1,3},{2,2,0},{2,2,2},{2,2,4},{2,3,1},{2,3,3},
  {3,0,3},{3,1,2},{3,1,4},{3,2,1},{3,2,3},{3,3,0},{3,3,2},{3,3,4}
};

__host__ __device__ constexpr double cfact(int n) {
  double r = 1.0;
  for (int i = 2; i <= n; ++i) r *= (double)i;
  return r;
}

__host__ __device__ constexpr double csqrt_(double x) {
  if (x <= 0.0) return 0.0;
  double g = x > 1.0 ? x : 1.0;
  for (int i = 0; i < 80; ++i) g = 0.5 * (g + x / g);
  return g;
}

struct CD { double re, im; };
__host__ __device__ constexpr CD cmul_(CD a, CD b) {
  return CD{ a.re*b.re - a.im*b.im, a.re*b.im + a.im*b.re };
}

struct QCol { int cnt; int m[2]; CD v[2]; };

__host__ __device__ constexpr QCol qcol(int l, int c) {
  QCol q{};
  const double is2 = 0.70710678118654752440;
  int mu = c - l;
  if (mu == 0) {
    q.cnt = 1; q.m[0] = 0; q.v[0] = CD{1.0, 0.0};
  } else if (mu > 0) {
    q.cnt = 2;
    q.m[0] = -mu; q.v[0] = CD{is2, 0.0};
    q.m[1] =  mu; q.v[1] = CD{(mu & 1) ? -is2 : is2, 0.0};
  } else {
    int am = -mu;
    q.cnt = 2;
    q.m[0] = -am; q.v[0] = CD{0.0, -is2};
    q.m[1] =  am; q.v[1] = CD{0.0, (am & 1) ? -is2 : is2};
  }
  CD ph{1.0, 0.0};
  switch (l & 3) {
    case 0: ph = CD{ 1.0,  0.0}; break;
    case 1: ph = CD{ 0.0, -1.0}; break;
    case 2: ph = CD{-1.0,  0.0}; break;
    default: ph = CD{ 0.0,  1.0}; break;
  }
  for (int t = 0; t < q.cnt; ++t) q.v[t] = cmul_(q.v[t], ph);
  return q;
}

__host__ __device__ constexpr double cgc(int j1, int m1, int j2, int m2, int j3, int m3) {
  if (m1 + m2 != m3) return 0.0;
  int vmin = -j1 + j2 + m3;
  if (-j1 + m1 > vmin) vmin = -j1 + m1;
  if (vmin < 0) vmin = 0;
  int vmax = j2 + j3 + m1;
  if (j3 - j1 + j2 < vmax) vmax = j3 - j1 + j2;
  if (j3 + m3 < vmax)      vmax = j3 + m3;
  if (vmax < vmin) return 0.0;
  double C = csqrt_((2.0*j3 + 1.0) * cfact(j3+j1-j2) * cfact(j3-j1+j2) * cfact(j1+j2-j3)
                    * cfact(j3+m3) * cfact(j3-m3)
                    / (cfact(j1+j2+j3+1) * cfact(j1-m1) * cfact(j1+m1)
                       * cfact(j2-m2) * cfact(j2+m2)));
  double S = 0.0;
  for (int v = vmin; v <= vmax; ++v) {
    double t = cfact(j2+j3+m1-v) * cfact(j1-m1+v)
             / (cfact(v) * cfact(j3-j1+j2-v) * cfact(j3+m3-v) * cfact(j1-j2-m3+v));
    S += ((v + j2 + m2) & 1) ? -t : t;
  }
  return C * S;
}

__host__ __device__ constexpr double w3j_raw(int l1, int l2, int l3, int i, int j, int k) {
  QCol q1 = qcol(l1, i), q2 = qcol(l2, j), q3 = qcol(l3, k);
  CD acc{0.0, 0.0};
  for (int x = 0; x < q1.cnt; ++x)
    for (int y = 0; y < q2.cnt; ++y)
      for (int z = 0; z < q3.cnt; ++z) {
        double cg = cgc(l1, q1.m[x], l2, q2.m[y], l3, q3.m[z]);
        if (cg != 0.0) {
          CD t = cmul_(cmul_(q1.v[x], q2.v[y]), q3.v[z]);
          acc.re += t.re * cg;
          acc.im += t.im * cg;
        }
      }
  return acc.re;
}

__host__ __device__ constexpr double w3j_norm(int l1, int l2, int l3) {
  double s = 0.0;
  int n1 = 2*l1 + 1, n2 = 2*l2 + 1, n3 = 2*l3 + 1;
  for (int i = 0; i < n1; ++i)
    for (int j = 0; j < n2; ++j)
      for (int k = 0; k < n3; ++k) {
        double v = w3j_raw(l1, l2, l3, i, j, k);
        s += v * v;
      }
  return csqrt_(s);
}

// ============================================================================
// Contraction via template recursion (all indices compile-time constants).
// Even parity => w3j(l2,l1,l3)[j,i,k] == w3j(l1,l2,l3)[i,j,k]; process only
// l1<=l2 triples with symmetrized products (and i<=j folding on the diagonal).
// ============================================================================

template <int T, int I, int J, int K>
__device__ __forceinline__ void kstep(float p, float (&acc)[25]) {
  constexpr int l1 = TRS[T].l1, l2 = TRS[T].l2, l3 = TRS[T].l3;
  constexpr int n3 = 2*l3 + 1, o3 = l3*l3;
  if constexpr (K < n3) {
    constexpr double wr = w3j_raw(l1, l2, l3, I, J, K);
    if constexpr (wr > 1e-12 || wr < -1e-12) {
      constexpr float w = (float)(wr / w3j_norm(l1, l2, l3));
      acc[o3 + K] = fmaf(p, w, acc[o3 + K]);
    }
    kstep<T, I, J, K + 1>(p, acc);
  }
}

template <int T, int I, int J>
__device__ __forceinline__ void jstep(const float (&a)[16], const float (&b)[16],
                                      float (&acc)[25]) {
  constexpr int l1 = TRS[T].l1, l2 = TRS[T].l2;
  constexpr int n2 = 2*l2 + 1, o1 = l1*l1, o2 = l2*l2;
  if constexpr (J < n2) {
    if constexpr (!(l1 == l2 && J < I)) {
      float p;
      if constexpr (l1 == l2) {
        if constexpr (J == I) p = a[o1 + I] * b[o2 + I];
        else                  p = a[o1 + I] * b[o2 + J] + a[o1 + J] * b[o2 + I];
      } else {
        p = a[o1 + I] * b[o2 + J] + a[o2 + J] * b[o1 + I];
      }
      kstep<T, I, J, 0>(p, acc);
    }
    jstep<T, I, J + 1>(a, b, acc);
  }
}

template <int T, int I>
__device__ __forceinline__ void istep(const float (&a)[16], const float (&b)[16],
                                      float (&acc)[25]) {
  constexpr int n1 = 2*TRS[T].l1 + 1;
  if constexpr (I < n1) {
    jstep<T, I, 0>(a, b, acc);
    istep<T, I + 1>(a, b, acc);
  }
}

template <int T>
__device__ __forceinline__ void contract_from(const float (&a)[16], const float (&b)[16],
                                              float (&acc)[25]) {
  if constexpr (T < NTRI) {
    if constexpr (TRS[T].l1 <= TRS[T].l2) {
      istep<T, 0>(a, b, acc);
    }
    contract_from<T + 1>(a, b, acc);
  }
}

// ============================================================================
// Main kernel. One thread per (node,channel) item. Per-warp smem staging:
// each warp owns an 800-float strip and drains it with __syncwarp only —
// no block-wide barriers anywhere in the main loop.
// ============================================================================
__global__ __launch_bounds__(256)
void tp_kernel(const float* __restrict__ A, const float* __restrict__ B,
               float* __restrict__ O, int nitems) {
  __shared__ float sstage[8 * 800];   // 8 warps x (32 items x 25 outputs)

  const int warp = threadIdx.x >> 5;
  const int lane = threadIdx.x & 31;
  float* swarp = sstage + warp * 800;
  const float4* sw4 = reinterpret_cast<const float4*>(swarp);

  for (int base = blockIdx.x * 256; base < nitems; base += gridDim.x * 256) {
    const int wbase = base + warp * 32;       // first item of this warp's group
    const int item  = wbase + lane;
    const bool valid = item < nitems;
    float a[16], b[16], acc[25];

    if (valid) {
      const float4* pa = reinterpret_cast<const float4*>(A) + (size_t)item * 4;
      const float4* pb = reinterpret_cast<const float4*>(B) + (size_t)item * 4;
      float4 v;
      v = pa[0]; a[ 0]=v.x; a[ 1]=v.y; a[ 2]=v.z; a[ 3]=v.w;
      v = pa[1]; a[ 4]=v.x; a[ 5]=v.y; a[ 6]=v.z; a[ 7]=v.w;
      v = pa[2]; a[ 8]=v.x; a[ 9]=v.y; a[10]=v.z; a[11]=v.w;
      v = pa[3]; a[12]=v.x; a[13]=v.y; a[14]=v.z; a[15]=v.w;
      v = pb[0]; b[ 0]=v.x; b[ 1]=v.y; b[ 2]=v.z; b[ 3]=v.w;
      v = pb[1]; b[ 4]=v.x; b[ 5]=v.y; b[ 6]=v.z; b[ 7]=v.w;
      v = pb[2]; b[ 8]=v.x; b[ 9]=v.y; b[10]=v.z; b[11]=v.w;
      v = pb[3]; b[12]=v.x; b[13]=v.y; b[14]=v.z; b[15]=v.w;
      #pragma unroll
      for (int k = 0; k < 25; ++k) acc[k] = 0.f;
      contract_from<0>(a, b, acc);
    }

    __syncwarp();   // previous group's staging reads are done
    if (valid) {
      #pragma unroll
      for (int k = 0; k < 25; ++k) swarp[lane * 25 + k] = acc[k];
    }
    __syncwarp();

    int vcnt = nitems - wbase;                 // items this warp group covers
    if (vcnt >= 32) {
      // 32 items * 25 floats = 800 floats = 200 float4, coalesced.
      float4* ov = reinterpret_cast<float4*>(O + (size_t)wbase * 25);
      #pragma unroll
      for (int r = 0; r < 6; ++r) ov[r * 32 + lane] = sw4[r * 32 + lane];
      if (lane < 8) ov[192 + lane] = sw4[192 + lane];
    } else if (vcnt > 0) {
      int cnt = vcnt * 25;
      float* op = O + (size_t)wbase * 25;
      for (int r = lane; r < cnt; r += 32) op[r] = swarp[r];
    }
  }
}

// ============================================================================
// Launch: persistent single wave (148 SMs x 3 resident CTAs at 80 regs).
// ============================================================================
extern "C" void kernel_launch(void* const* d_in, const int* in_sizes, int n_in,
                              void* d_out, int out_size) {
  const float* A = (const float*)d_in[0];
  const float* B = (const float*)d_in[1];
  float* O = (float*)d_out;
  int nitems = in_sizes[0] / 16;
  if (nitems <= 0) return;

  int chunks = (nitems + 255) / 256;
  int grid = chunks < 444 ? chunks : 444;
  tp_kernel<<<grid, 256>>>(A, B, O, nitems);
}

// round 6
// speedup vs baseline: 1.6339x; 1.0155x over previous
#include <cuda_runtime.h>

// ============================================================================
// Compile-time real Wigner-3j coefficients.
// All math in constexpr double; values baked into SASS as FFMA immediates.
// ============================================================================
#define NTRI 27

struct Tri { int l1, l2, l3; };
constexpr Tri TRS[NTRI] = {
  {0,0,0},{0,1,1},{0,2,2},{0,3,3},
  {1,0,1},{1,1,0},{1,1,2},{1,2,1},{1,2,3},{1,3,2},{1,3,4},
  {2,0,2},{2,1,1},{2,1,3},{2,2,0},{2,2,2},{2,2,4},{2,3,1},{2,3,3},
  {3,0,3},{3,1,2},{3,1,4},{3,2,1},{3,2,3},{3,3,0},{3,3,2},{3,3,4}
};

__host__ __device__ constexpr double cfact(int n) {
  double r = 1.0;
  for (int i = 2; i <= n; ++i) r *= (double)i;
  return r;
}

__host__ __device__ constexpr double csqrt_(double x) {
  if (x <= 0.0) return 0.0;
  double g = x > 1.0 ? x : 1.0;
  for (int i = 0; i < 80; ++i) g = 0.5 * (g + x / g);
  return g;
}

struct CD { double re, im; };
__host__ __device__ constexpr CD cmul_(CD a, CD b) {
  return CD{ a.re*b.re - a.im*b.im, a.re*b.im + a.im*b.re };
}

struct QCol { int cnt; int m[2]; CD v[2]; };

__host__ __device__ constexpr QCol qcol(int l, int c) {
  QCol q{};
  const double is2 = 0.70710678118654752440;
  int mu = c - l;
  if (mu == 0) {
    q.cnt = 1; q.m[0] = 0; q.v[0] = CD{1.0, 0.0};
  } else if (mu > 0) {
    q.cnt = 2;
    q.m[0] = -mu; q.v[0] = CD{is2, 0.0};
    q.m[1] =  mu; q.v[1] = CD{(mu & 1) ? -is2 : is2, 0.0};
  } else {
    int am = -mu;
    q.cnt = 2;
    q.m[0] = -am; q.v[0] = CD{0.0, -is2};
    q.m[1] =  am; q.v[1] = CD{0.0, (am & 1) ? -is2 : is2};
  }
  CD ph{1.0, 0.0};
  switch (l & 3) {
    case 0: ph = CD{ 1.0,  0.0}; break;
    case 1: ph = CD{ 0.0, -1.0}; break;
    case 2: ph = CD{-1.0,  0.0}; break;
    default: ph = CD{ 0.0,  1.0}; break;
  }
  for (int t = 0; t < q.cnt; ++t) q.v[t] = cmul_(q.v[t], ph);
  return q;
}

__host__ __device__ constexpr double cgc(int j1, int m1, int j2, int m2, int j3, int m3) {
  if (m1 + m2 != m3) return 0.0;
  int vmin = -j1 + j2 + m3;
  if (-j1 + m1 > vmin) vmin = -j1 + m1;
  if (vmin < 0) vmin = 0;
  int vmax = j2 + j3 + m1;
  if (j3 - j1 + j2 < vmax) vmax = j3 - j1 + j2;
  if (j3 + m3 < vmax)      vmax = j3 + m3;
  if (vmax < vmin) return 0.0;
  double C = csqrt_((2.0*j3 + 1.0) * cfact(j3+j1-j2) * cfact(j3-j1+j2) * cfact(j1+j2-j3)
                    * cfact(j3+m3) * cfact(j3-m3)
                    / (cfact(j1+j2+j3+1) * cfact(j1-m1) * cfact(j1+m1)
                       * cfact(j2-m2) * cfact(j2+m2)));
  double S = 0.0;
  for (int v = vmin; v <= vmax; ++v) {
    double t = cfact(j2+j3+m1-v) * cfact(j1-m1+v)
             / (cfact(v) * cfact(j3-j1+j2-v) * cfact(j3+m3-v) * cfact(j1-j2-m3+v));
    S += ((v + j2 + m2) & 1) ? -t : t;
  }
  return C * S;
}

__host__ __device__ constexpr double w3j_raw(int l1, int l2, int l3, int i, int j, int k) {
  QCol q1 = qcol(l1, i), q2 = qcol(l2, j), q3 = qcol(l3, k);
  CD acc{0.0, 0.0};
  for (int x = 0; x < q1.cnt; ++x)
    for (int y = 0; y < q2.cnt; ++y)
      for (int z = 0; z < q3.cnt; ++z) {
        double cg = cgc(l1, q1.m[x], l2, q2.m[y], l3, q3.m[z]);
        if (cg != 0.0) {
          CD t = cmul_(cmul_(q1.v[x], q2.v[y]), q3.v[z]);
          acc.re += t.re * cg;
          acc.im += t.im * cg;
        }
      }
  return acc.re;
}

__host__ __device__ constexpr double w3j_norm(int l1, int l2, int l3) {
  double s = 0.0;
  int n1 = 2*l1 + 1, n2 = 2*l2 + 1, n3 = 2*l3 + 1;
  for (int i = 0; i < n1; ++i)
    for (int j = 0; j < n2; ++j)
      for (int k = 0; k < n3; ++k) {
        double v = w3j_raw(l1, l2, l3, i, j, k);
        s += v * v;
      }
  return csqrt_(s);
}

// ============================================================================
// Contraction via template recursion (all indices compile-time constants).
// Even parity => w3j(l2,l1,l3)[j,i,k] == w3j(l1,l2,l3)[i,j,k]; process only
// l1<=l2 triples with symmetrized products (and i<=j folding on the diagonal).
// ============================================================================

template <int T, int I, int J, int K>
__device__ __forceinline__ void kstep(float p, float (&acc)[25]) {
  constexpr int l1 = TRS[T].l1, l2 = TRS[T].l2, l3 = TRS[T].l3;
  constexpr int n3 = 2*l3 + 1, o3 = l3*l3;
  if constexpr (K < n3) {
    constexpr double wr = w3j_raw(l1, l2, l3, I, J, K);
    if constexpr (wr > 1e-12 || wr < -1e-12) {
      constexpr float w = (float)(wr / w3j_norm(l1, l2, l3));
      acc[o3 + K] = fmaf(p, w, acc[o3 + K]);
    }
    kstep<T, I, J, K + 1>(p, acc);
  }
}

template <int T, int I, int J>
__device__ __forceinline__ void jstep(const float (&a)[16], const float (&b)[16],
                                      float (&acc)[25]) {
  constexpr int l1 = TRS[T].l1, l2 = TRS[T].l2;
  constexpr int n2 = 2*l2 + 1, o1 = l1*l1, o2 = l2*l2;
  if constexpr (J < n2) {
    if constexpr (!(l1 == l2 && J < I)) {
      float p;
      if constexpr (l1 == l2) {
        if constexpr (J == I) p = a[o1 + I] * b[o2 + I];
        else                  p = a[o1 + I] * b[o2 + J] + a[o1 + J] * b[o2 + I];
      } else {
        p = a[o1 + I] * b[o2 + J] + a[o2 + J] * b[o1 + I];
      }
      kstep<T, I, J, 0>(p, acc);
    }
    jstep<T, I, J + 1>(a, b, acc);
  }
}

template <int T, int I>
__device__ __forceinline__ void istep(const float (&a)[16], const float (&b)[16],
                                      float (&acc)[25]) {
  constexpr int n1 = 2*TRS[T].l1 + 1;
  if constexpr (I < n1) {
    jstep<T, I, 0>(a, b, acc);
    istep<T, I + 1>(a, b, acc);
  }
}

template <int T>
__device__ __forceinline__ void contract_from(const float (&a)[16], const float (&b)[16],
                                              float (&acc)[25]) {
  if constexpr (T < NTRI) {
    if constexpr (TRS[T].l1 <= TRS[T].l2) {
      istep<T, 0>(a, b, acc);
    }
    contract_from<T + 1>(a, b, acc);
  }
}

// Load one item's 16-float irrep vector as 4 float4s.
__device__ __forceinline__ void load16(const float* __restrict__ P, int item,
                                       float (&r)[16]) {
  const float4* p4 = reinterpret_cast<const float4*>(P) + (size_t)item * 4;
  float4 v;
  v = p4[0]; r[ 0]=v.x; r[ 1]=v.y; r[ 2]=v.z; r[ 3]=v.w;
  v = p4[1]; r[ 4]=v.x; r[ 5]=v.y; r[ 6]=v.z; r[ 7]=v.w;
  v = p4[2]; r[ 8]=v.x; r[ 9]=v.y; r[10]=v.z; r[11]=v.w;
  v = p4[3]; r[12]=v.x; r[13]=v.y; r[14]=v.z; r[15]=v.w;
}

// ============================================================================
// Main kernel. One thread per (node,channel) item; software-pipelined register
// prefetch of the next grid-stride chunk; per-warp smem staging drained with
// __syncwarp only (no block barriers in the loop).
// ============================================================================
__global__ __launch_bounds__(256, 2)
void tp_kernel(const float* __restrict__ A, const float* __restrict__ B,
               float* __restrict__ O, int nitems) {
  __shared__ float sstage[8 * 800];   // 8 warps x (32 items x 25 outputs)

  const int warp = threadIdx.x >> 5;
  const int lane = threadIdx.x & 31;
  float* swarp = sstage + warp * 800;
  const float4* sw4 = reinterpret_cast<const float4*>(swarp);

  const int stride = gridDim.x * 256;
  int base = blockIdx.x * 256;
  if (base >= nitems) return;

  // Prologue: load first chunk (clamped; stores are guarded later).
  float a[16], b[16];
  {
    int item = base + warp * 32 + lane;
    int it = item < nitems ? item : nitems - 1;
    load16(A, it, a);
    load16(B, it, b);
  }

  for (; base < nitems; ) {
    const int nextbase = base + stride;

    // Prefetch next chunk before touching current data.
    float an[16], bn[16];
    if (nextbase < nitems) {
      int item = nextbase + warp * 32 + lane;
      int it = item < nitems ? item : nitems - 1;
      load16(A, it, an);
      load16(B, it, bn);
    }

    // Contract current chunk.
    float acc[25];
    #pragma unroll
    for (int k = 0; k < 25; ++k) acc[k] = 0.f;
    contract_from<0>(a, b, acc);

    // Stage and drain this warp's 32x25 outputs.
    const int wbase = base + warp * 32;
    const bool valid = (wbase + lane) < nitems;
    __syncwarp();   // previous group's staging reads are done
    if (valid) {
      #pragma unroll
      for (int k = 0; k < 25; ++k) swarp[lane * 25 + k] = acc[k];
    }
    __syncwarp();

    int vcnt = nitems - wbase;
    if (vcnt >= 32) {
      float4* ov = reinterpret_cast<float4*>(O + (size_t)wbase * 25);
      #pragma unroll
      for (int r = 0; r < 6; ++r) ov[r * 32 + lane] = sw4[r * 32 + lane];
      if (lane < 8) ov[192 + lane] = sw4[192 + lane];
    } else if (vcnt > 0) {
      int cnt = vcnt * 25;
      float* op = O + (size_t)wbase * 25;
      for (int r = lane; r < cnt; r += 32) op[r] = swarp[r];
    }

    // Rotate prefetched registers into current.
    #pragma unroll
    for (int k = 0; k < 16; ++k) { a[k] = an[k]; b[k] = bn[k]; }
    base = nextbase;
  }
}

// ============================================================================
// Launch: persistent single wave (148 SMs x 2 resident CTAs at <=128 regs).
// ============================================================================
extern "C" void kernel_launch(void* const* d_in, const int* in_sizes, int n_in,
                              void* d_out, int out_size) {
  const float* A = (const float*)d_in[0];
  const float* B = (const float*)d_in[1];
  float* O = (float*)d_out;
  int nitems = in_sizes[0] / 16;
  if (nitems <= 0) return;

  int chunks = (nitems + 255) / 256;
  int grid = chunks < 296 ? chunks : 296;
  tp_kernel<<<grid, 256>>>(A, B, O, nitems);
}